// round 12
// baseline (speedup 1.0000x reference)
#include <cuda_runtime.h>
#include <cstdint>

#define BB 256
#define CC 768
#define LL 256
#define PP 3
#define MINUS_F (-100.0f)
#define BIAS_F  (-200.0f)

#define ROWS_PER_BLOCK 64
#define NWARPS 8
#define ROWS_PER_WARP (ROWS_PER_BLOCK / NWARPS)   // 8
#define THREADS (NWARPS * 32)

// Force 5 resident blocks/SM (<=51 regs): 40 warps/SM to cover DRAM + SHFL latency.
__global__ __launch_bounds__(THREADS, 5) void piece_max_pool_kernel(
    const float* __restrict__ x,
    const int*   __restrict__ m32,   // int32 view of mask buffer (int32 or int64 data)
    float*       __restrict__ out)
{
    const int b    = blockIdx.x;
    const int c0   = blockIdx.y * ROWS_PER_BLOCK;
    const int tid  = threadIdx.x;
    const int warp = tid >> 5;
    const int lane = tid & 31;

    // ---- In-kernel dtype detection (single launch) ----
    // First 512 int32 slots are valid for BOTH layouts:
    //  int64 mask: odd slots = high words == 0 (values in [0,3]).
    //  int32 mask: odd slots = 256 random values in 0..3 -> some nonzero.
    const int probe = m32[2 * tid + 1];
    const bool is64 = (__syncthreads_or(probe != 0) == 0);

    // ---- Per-lane mask values for this lane's 8 fixed L positions ----
    //   l = h*128 + lane*4 + j,  h in {0,1}, j in {0..3}
    int mv[8];
    const int base = b * LL;
    if (is64) {
#pragma unroll
        for (int h = 0; h < 2; ++h) {
            const int4* mp = reinterpret_cast<const int4*>(m32 + 2 * (base + h * 128));
            const int4 q0 = mp[2 * lane];
            const int4 q1 = mp[2 * lane + 1];
            mv[h * 4 + 0] = q0.x;  mv[h * 4 + 1] = q0.z;
            mv[h * 4 + 2] = q1.x;  mv[h * 4 + 3] = q1.z;
        }
    } else {
#pragma unroll
        for (int h = 0; h < 2; ++h) {
            const int4 q = reinterpret_cast<const int4*>(m32 + base + h * 128)[lane];
            mv[h * 4 + 0] = q.x;  mv[h * 4 + 1] = q.y;
            mv[h * 4 + 2] = q.z;  mv[h * 4 + 3] = q.w;
        }
    }

    // ---- Additive biases, computed ONCE, reused across all 8 rows ----
    // bias_p[j] = 0 if mv[j]==p+1 else -200.  Accumulation = FADD (fma pipe)
    // + FMNMX (alu pipe): balanced pipes, no per-row ISETP chains.
    float bias0[8], bias1[8], bias2[8];
#pragma unroll
    for (int j = 0; j < 8; ++j) {
        bias0[j] = (mv[j] == 1) ? 0.0f : BIAS_F;
        bias1[j] = (mv[j] == 2) ? 0.0f : BIAS_F;
        bias2[j] = (mv[j] == 3) ? 0.0f : BIAS_F;
    }

    const int c_base = c0 + warp * ROWS_PER_WARP;
    const float4* xp = reinterpret_cast<const float4*>(
        x + (size_t)(b * CC + c_base) * LL);
    float* const outb = out + (size_t)b * (PP * CC);

    // Software pipeline: prefetch row r+1 before reducing row r.
    // Streaming loads: x is read exactly once, don't pollute L2.
    float4 n0 = __ldcs(xp + lane);
    float4 n1 = __ldcs(xp + lane + 32);

#pragma unroll
    for (int r = 0; r < ROWS_PER_WARP; ++r) {
        const float4 v0 = n0;
        const float4 v1 = n1;
        if (r < ROWS_PER_WARP - 1) {
            xp += LL / 4;
            n0 = __ldcs(xp + lane);
            n1 = __ldcs(xp + lane + 32);
        }

        float g  = -1e30f;
        float a0 = -1e30f, a1 = -1e30f, a2 = -1e30f;

        const float vv[8] = {v0.x, v0.y, v0.z, v0.w, v1.x, v1.y, v1.z, v1.w};
#pragma unroll
        for (int j = 0; j < 8; ++j) {
            const float v = vv[j];
            g  = fmaxf(g,  v);
            a0 = fmaxf(a0, v + bias0[j]);
            a1 = fmaxf(a1, v + bias1[j]);
            a2 = fmaxf(a2, v + bias2[j]);
        }

        // ---- Multi-value butterfly over {g,a0,a1,a2}: 7 SHFL total ----
        // Step 0 (xor 1): lanes bit0=0 keep {g,a0}, bit0=1 keep {a1,a2}.
        const bool up1 = lane & 1;
        {
            const float s0 = up1 ? g  : a1;
            const float s1 = up1 ? a0 : a2;
            const float r0 = __shfl_xor_sync(0xFFFFFFFFu, s0, 1);
            const float r1 = __shfl_xor_sync(0xFFFFFFFFu, s1, 1);
            const float k0 = up1 ? a1 : g;
            const float k1 = up1 ? a2 : a0;
            g  = fmaxf(k0, r0);   // kept value 0
            a0 = fmaxf(k1, r1);   // kept value 1
        }
        // Step 1 (xor 2): bit1 picks within the kept pair.
        const bool up2 = lane & 2;
        float v = up2 ? a0 : g;
        {
            const float s = up2 ? g : a0;
            const float rr = __shfl_xor_sync(0xFFFFFFFFu, s, 2);
            v = fmaxf(v, rr);
        }
        // Steps 2..4: plain reduce of the single kept value.
        v = fmaxf(v, __shfl_xor_sync(0xFFFFFFFFu, v, 4));
        v = fmaxf(v, __shfl_xor_sync(0xFFFFFFFFu, v, 8));
        v = fmaxf(v, __shfl_xor_sync(0xFFFFFFFFu, v, 16));

        // Mapping proven in R8: lane1 -> piece 1, lane2 -> piece 0, lane3 -> piece 2.
        const float g_row = __shfl_sync(0xFFFFFFFFu, v, 0);

        if (lane >= 1 && lane <= 3) {
            const int piece = (lane == 2) ? 0 : ((lane == 1) ? 1 : 2);
            outb[piece * CC + (c_base + r)] = fmaxf(v, g_row + MINUS_F);
        }
    }
}

extern "C" void kernel_launch(void* const* d_in, const int* in_sizes, int n_in,
                              void* d_out, int out_size)
{
    const float* x = (const float*)d_in[0];
    const int*   m = (const int*)d_in[1];   // int32 view of mask buffer
    float* out = (float*)d_out;

    dim3 grid(BB, CC / ROWS_PER_BLOCK);
    piece_max_pool_kernel<<<grid, THREADS>>>(x, m, out);
}